// round 8
// baseline (speedup 1.0000x reference)
#include <cuda_runtime.h>
#include <cuda_bf16.h>
#include <cstdint>

// Problem constants
#define BB   4
#define SS   2048
#define HH   16
#define DH   64
#define DM   1024
#define BHT  (BB*HH)          // 64

// Scratch (device globals). g_qh/g_kh/g_vh/g_ctx hold tf32-rounded values
// (bit patterns in fp32 containers) — consumers feed them straight to MMA.
__device__ float g_qh [(size_t)BB*HH*SS*DH];
__device__ float g_kh [(size_t)BB*HH*SS*DH];
__device__ float g_vh [(size_t)BB*HH*SS*DH];
__device__ float g_ctx[(size_t)BB*HH*SS*DH];

// fp32 -> tf32 round-to-nearest
__device__ __forceinline__ uint32_t tf32c(float x) {
    uint32_t u;
    asm("cvt.rna.tf32.f32 %0, %1;" : "=r"(u) : "f"(x));
    return u;
}

// m16n8k8 tf32 MMA, fp32 accumulate
__device__ __forceinline__ void mma8(float c[4], const uint32_t a[4], const uint32_t b[2]) {
    asm volatile(
        "mma.sync.aligned.m16n8k8.row.col.f32.tf32.tf32.f32 "
        "{%0,%1,%2,%3},{%4,%5,%6,%7},{%8,%9},{%0,%1,%2,%3};"
        : "+f"(c[0]), "+f"(c[1]), "+f"(c[2]), "+f"(c[3])
        : "r"(a[0]), "r"(a[1]), "r"(a[2]), "r"(a[3]), "r"(b[0]), "r"(b[1]));
}

// cp.async helpers
__device__ __forceinline__ void cpa16(uint32_t saddr, const void* g) {
    asm volatile("cp.async.ca.shared.global [%0], [%1], 16;" :: "r"(saddr), "l"(g));
}
#define CP_COMMIT asm volatile("cp.async.commit_group;")
#define CP_WAIT0  asm volatile("cp.async.wait_group 0;")
#define CP_WAIT1  asm volatile("cp.async.wait_group 1;")

// ---------------------------------------------------------------------------
// K1: fused QKV projection. 128x128 tile, 64x32 warp tiles, BK=16.
// cp.async double buffer; epilogue stores tf32-rounded values.
// ---------------------------------------------------------------------------
__global__ __launch_bounds__(256, 2) void k_qkv_proj(
    const float* __restrict__ xq, const float* __restrict__ xk, const float* __restrict__ xv,
    const float* __restrict__ wq, const float* __restrict__ wk, const float* __restrict__ wv,
    const float* __restrict__ bq, const float* __restrict__ bk, const float* __restrict__ bv)
{
    __shared__ float As[2][2560];
    __shared__ float Bs[2][2560];
    int z = blockIdx.z;
    const float* X  = (z == 0) ? xq : (z == 1) ? xk : xv;
    const float* W  = (z == 0) ? wq : (z == 1) ? wk : wv;
    const float* Bi = (z == 0) ? bq : (z == 1) ? bk : bv;
    float*       O  = (z == 0) ? g_qh : (z == 1) ? g_kh : g_vh;

    int tid = threadIdx.x;
    int lane = tid & 31, wid = tid >> 5;
    int g = lane >> 2, ct = lane & 3;
    int mb = (wid >> 2) * 64, nb = (wid & 3) * 32;
    int m0 = blockIdx.y * 128, n0 = blockIdx.x * 128;

    uint32_t asb = (uint32_t)__cvta_generic_to_shared(&As[0][0]);
    uint32_t bsb = (uint32_t)__cvta_generic_to_shared(&Bs[0][0]);
    int rl = tid >> 2, cl = (tid & 3) << 2;

    float c[4][4][4];
    #pragma unroll
    for (int i = 0; i < 4; i++)
        #pragma unroll
        for (int j = 0; j < 4; j++)
            #pragma unroll
            for (int t = 0; t < 4; t++) c[i][j][t] = 0.0f;

    cpa16(asb + (0 * 2560 + rl * 20 + cl) * 4,        X + (size_t)(m0 + rl) * DM + cl);
    cpa16(asb + (0 * 2560 + (rl + 64) * 20 + cl) * 4, X + (size_t)(m0 + rl + 64) * DM + cl);
    cpa16(bsb + (0 * 2560 + rl * 20 + cl) * 4,        W + (size_t)(n0 + rl) * DM + cl);
    cpa16(bsb + (0 * 2560 + (rl + 64) * 20 + cl) * 4, W + (size_t)(n0 + rl + 64) * DM + cl);
    CP_COMMIT;

    for (int k0 = 0, st = 0; k0 < DM; k0 += 16, st ^= 1) {
        CP_WAIT0;
        __syncthreads();
        if (k0 + 16 < DM) {
            int kn = k0 + 16, so = (st ^ 1) * 2560;
            cpa16(asb + (so + rl * 20 + cl) * 4,        X + (size_t)(m0 + rl) * DM + kn + cl);
            cpa16(asb + (so + (rl + 64) * 20 + cl) * 4, X + (size_t)(m0 + rl + 64) * DM + kn + cl);
            cpa16(bsb + (so + rl * 20 + cl) * 4,        W + (size_t)(n0 + rl) * DM + kn + cl);
            cpa16(bsb + (so + (rl + 64) * 20 + cl) * 4, W + (size_t)(n0 + rl + 64) * DM + kn + cl);
        }
        CP_COMMIT;
        const float* Af = &As[st][0];
        const float* Bf = &Bs[st][0];
        #pragma unroll
        for (int ks = 0; ks < 16; ks += 8) {
            uint32_t af[4][4], bf[4][2];
            #pragma unroll
            for (int i = 0; i < 4; i++) {
                int r0 = (mb + i * 16 + g) * 20 + ks + ct;
                af[i][0] = tf32c(Af[r0]);       af[i][2] = tf32c(Af[r0 + 4]);
                af[i][1] = tf32c(Af[r0 + 160]); af[i][3] = tf32c(Af[r0 + 164]);
            }
            #pragma unroll
            for (int j = 0; j < 4; j++) {
                int b0 = (nb + j * 8 + g) * 20 + ks + ct;
                bf[j][0] = tf32c(Bf[b0]); bf[j][1] = tf32c(Bf[b0 + 4]);
            }
            #pragma unroll
            for (int i = 0; i < 4; i++)
                #pragma unroll
                for (int j = 0; j < 4; j++) mma8(c[i][j], af[i], bf[j]);
        }
    }
    __syncthreads();
    // epilogue: bias add (fp32) then tf32 round; scatter to [B,H,S,Dh]
    #pragma unroll
    for (int i = 0; i < 4; i++) {
        int row = m0 + mb + i * 16 + g;
        int b_ = row >> 11, s_ = row & (SS - 1);
        #pragma unroll
        for (int j = 0; j < 4; j++) {
            int col = n0 + nb + j * 8 + ct * 2;
            int h = col >> 6, dh = col & 63;
            float2 bi = *(const float2*)&Bi[col];
            size_t base = ((size_t)(b_ * HH + h) * SS + s_) * DH + dh;
            *(float2*)&O[base] = make_float2(
                __uint_as_float(tf32c(c[i][j][0] + bi.x)),
                __uint_as_float(tf32c(c[i][j][1] + bi.y)));
            *(float2*)&O[base + 8 * DH] = make_float2(
                __uint_as_float(tf32c(c[i][j][2] + bi.x)),
                __uint_as_float(tf32c(c[i][j][3] + bi.y)));
        }
    }
}

// ---------------------------------------------------------------------------
// K2: fused attention, 512 threads / 16 warps.
// QK warp tile 32q x 32n; PV warp tile 16dh x 32q. cp.async pipelined.
// Q/K/V arrive pre-rounded tf32 -> no cvt in inner loops.
// ---------------------------------------------------------------------------
#define AT_QS  0
#define AT_KS  8704
#define AT_VS  26112
#define AT_PS  35328
#define AT_RP  52224
#define AT_INV 52736
#define AT_WORDS 52864
#define AT_BYTES (AT_WORDS * 4)

__global__ __launch_bounds__(512, 1) void k_attn(
    const float* __restrict__ mask, float* __restrict__ score)
{
    extern __shared__ uint32_t sm[];
    uint32_t* Qs = sm + AT_QS;
    float* Ksf   = (float*)(sm + AT_KS);
    float* Vsf   = (float*)(sm + AT_VS);
    uint32_t* Ps = sm + AT_PS;
    float* rowp  = (float*)(sm + AT_RP);
    float* invs  = (float*)(sm + AT_INV);
    uint32_t smb = (uint32_t)__cvta_generic_to_shared(sm);

    int bh = blockIdx.y, q0 = blockIdx.x * 128;
    const float* Q = g_qh + (size_t)bh * SS * DH;
    const float* K = g_kh + (size_t)bh * SS * DH;
    const float* V = g_vh + (size_t)bh * SS * DH;

    int tid = threadIdx.x, lane = tid & 31, wid = tid >> 5;   // wid 0..15
    int g = lane >> 2, ct = lane & 3;
    int mb = (wid >> 2) * 32, nb = (wid & 3) * 32;   // QK warp tile 32x32
    int pm = (wid & 3) * 16, pn = (wid >> 2) * 32;   // PV warp tile 16dh x 32q

    // Q tile -> smem (already tf32 bits; plain copy)
    #pragma unroll
    for (int it = 0; it < 4; it++) {
        int fi = tid + it * 512;
        int r = fi >> 4, c4 = (fi & 15) << 2;
        float4 a = *(const float4*)(Q + (size_t)(q0 + r) * DH + c4);
        *(uint4*)&Qs[r * 68 + c4] = make_uint4(__float_as_uint(a.x), __float_as_uint(a.y),
                                               __float_as_uint(a.z), __float_as_uint(a.w));
    }

    float c[2][4][4];
    float rs[2][2];
    #pragma unroll
    for (int i = 0; i < 2; i++) { rs[i][0] = 0.0f; rs[i][1] = 0.0f; }

    // ---------------- Pass A: row sums ----------------
    #pragma unroll
    for (int it = 0; it < 4; it++) {
        int fi = tid + it * 512;
        int r = fi >> 4, c4 = (fi & 15) << 2;
        cpa16(smb + (AT_KS + r * 68 + c4) * 4, K + (size_t)r * DH + c4);
    }
    CP_COMMIT;

    for (int n0 = 0, st = 0; n0 < SS; n0 += 128, st ^= 1) {
        CP_WAIT0;
        __syncthreads();
        if (n0 + 128 < SS) {
            int so = AT_KS + (st ^ 1) * 8704;
            #pragma unroll
            for (int it = 0; it < 4; it++) {
                int fi = tid + it * 512;
                int r = fi >> 4, c4 = (fi & 15) << 2;
                cpa16(smb + (so + r * 68 + c4) * 4, K + (size_t)(n0 + 128 + r) * DH + c4);
            }
        }
        CP_COMMIT;
        const float* Kf = Ksf + st * 8704;
        #pragma unroll
        for (int i = 0; i < 2; i++)
            #pragma unroll
            for (int j = 0; j < 4; j++)
                #pragma unroll
                for (int t = 0; t < 4; t++) c[i][j][t] = 0.0f;
        #pragma unroll
        for (int ks = 0; ks < DH; ks += 8) {
            uint32_t af[2][4], bf[4][2];
            #pragma unroll
            for (int i = 0; i < 2; i++) {
                int r0 = (mb + i * 16 + g) * 68 + ks + ct;
                af[i][0] = Qs[r0];       af[i][2] = Qs[r0 + 4];
                af[i][1] = Qs[r0 + 544]; af[i][3] = Qs[r0 + 548];
            }
            #pragma unroll
            for (int j = 0; j < 4; j++) {
                int b0 = (nb + j * 8 + g) * 68 + ks + ct;
                bf[j][0] = __float_as_uint(Kf[b0]); bf[j][1] = __float_as_uint(Kf[b0 + 4]);
            }
            #pragma unroll
            for (int i = 0; i < 2; i++)
                #pragma unroll
                for (int j = 0; j < 4; j++) mma8(c[i][j], af[i], bf[j]);
        }
        #pragma unroll
        for (int i = 0; i < 2; i++) {
            int row = q0 + mb + i * 16 + g;
            #pragma unroll
            for (int j = 0; j < 4; j++) {
                int colg = n0 + nb + j * 8 + ct * 2;
                float2 mk0 = *(const float2*)&mask[(size_t)row * SS + colg];
                rs[i][0] += __expf(fmaf(c[i][j][0], 0.125f, mk0.x))
                          + __expf(fmaf(c[i][j][1], 0.125f, mk0.y));
                float2 mk1 = *(const float2*)&mask[(size_t)(row + 8) * SS + colg];
                rs[i][1] += __expf(fmaf(c[i][j][2], 0.125f, mk1.x))
                          + __expf(fmaf(c[i][j][3], 0.125f, mk1.y));
            }
        }
    }
    #pragma unroll
    for (int i = 0; i < 2; i++) {
        #pragma unroll
        for (int hh = 0; hh < 2; hh++) {
            float v = rs[i][hh];
            v += __shfl_xor_sync(0xffffffff, v, 1);
            v += __shfl_xor_sync(0xffffffff, v, 2);
            if (ct == 0) rowp[(mb + i * 16 + hh * 8 + g) * 4 + (wid & 3)] = v;
        }
    }
    __syncthreads();
    if (tid < 128)
        invs[tid] = 1.0f / (rowp[tid*4] + rowp[tid*4+1] + rowp[tid*4+2] + rowp[tid*4+3]);

    // ---------------- Pass B: score + ctx ----------------
    float d[4][4];
    #pragma unroll
    for (int j = 0; j < 4; j++)
        #pragma unroll
        for (int t = 0; t < 4; t++) d[j][t] = 0.0f;

    size_t sbase = (size_t)bh * SS * SS;

    #pragma unroll
    for (int it = 0; it < 4; it++) {
        int fi = tid + it * 512;
        int r = fi >> 4, c4 = (fi & 15) << 2;
        cpa16(smb + (AT_KS + r * 68 + c4) * 4, K + (size_t)r * DH + c4);
    }
    CP_COMMIT;

    for (int n0 = 0, st = 0; n0 < SS; n0 += 128, st ^= 1) {
        CP_WAIT0;            // K_cur ready
        __syncthreads();     // prev PV readers done; invs visible (iter 0)
        #pragma unroll
        for (int it = 0; it < 4; it++) {
            int fi = tid + it * 512;
            int r = fi >> 4, c4 = (fi & 15) << 2;
            cpa16(smb + (AT_VS + r * 72 + c4) * 4, V + (size_t)(n0 + r) * DH + c4);
        }
        CP_COMMIT;
        if (n0 + 128 < SS) {
            int so = AT_KS + (st ^ 1) * 8704;
            #pragma unroll
            for (int it = 0; it < 4; it++) {
                int fi = tid + it * 512;
                int r = fi >> 4, c4 = (fi & 15) << 2;
                cpa16(smb + (so + r * 68 + c4) * 4, K + (size_t)(n0 + 128 + r) * DH + c4);
            }
        }
        CP_COMMIT;

        const float* Kf = Ksf + st * 8704;
        #pragma unroll
        for (int i = 0; i < 2; i++)
            #pragma unroll
            for (int j = 0; j < 4; j++)
                #pragma unroll
                for (int t = 0; t < 4; t++) c[i][j][t] = 0.0f;
        #pragma unroll
        for (int ks = 0; ks < DH; ks += 8) {
            uint32_t af[2][4], bf[4][2];
            #pragma unroll
            for (int i = 0; i < 2; i++) {
                int r0 = (mb + i * 16 + g) * 68 + ks + ct;
                af[i][0] = Qs[r0];       af[i][2] = Qs[r0 + 4];
                af[i][1] = Qs[r0 + 544]; af[i][3] = Qs[r0 + 548];
            }
            #pragma unroll
            for (int j = 0; j < 4; j++) {
                int b0 = (nb + j * 8 + g) * 68 + ks + ct;
                bf[j][0] = __float_as_uint(Kf[b0]); bf[j][1] = __float_as_uint(Kf[b0 + 4]);
            }
            #pragma unroll
            for (int i = 0; i < 2; i++)
                #pragma unroll
                for (int j = 0; j < 4; j++) mma8(c[i][j], af[i], bf[j]);
        }
        // epilogue: p = exp(s)*inv -> score gmem (once) + Ps smem (tf32)
        #pragma unroll
        for (int i = 0; i < 2; i++) {
            int rloc = mb + i * 16 + g;
            float iv0 = invs[rloc], iv1 = invs[rloc + 8];
            int grow = q0 + rloc;
            #pragma unroll
            for (int j = 0; j < 4; j++) {
                int col = nb + j * 8 + ct * 2;
                int colg = n0 + col;
                float2 mk0 = *(const float2*)&mask[(size_t)grow * SS + colg];
                float p0 = __expf(fmaf(c[i][j][0], 0.125f, mk0.x)) * iv0;
                float p1 = __expf(fmaf(c[i][j][1], 0.125f, mk0.y)) * iv0;
                *(float2*)&score[sbase + (size_t)grow * SS + colg] = make_float2(p0, p1);
                Ps[rloc * 132 + col]     = tf32c(p0);
                Ps[rloc * 132 + col + 1] = tf32c(p1);
                float2 mk1 = *(const float2*)&mask[(size_t)(grow + 8) * SS + colg];
                float p2 = __expf(fmaf(c[i][j][2], 0.125f, mk1.x)) * iv1;
                float p3 = __expf(fmaf(c[i][j][3], 0.125f, mk1.y)) * iv1;
                *(float2*)&score[sbase + (size_t)(grow + 8) * SS + colg] = make_float2(p2, p3);
                Ps[(rloc + 8) * 132 + col]     = tf32c(p2);
                Ps[(rloc + 8) * 132 + col + 1] = tf32c(p3);
            }
        }
        CP_WAIT1;            // V_cur done (K_next may remain in flight)
        __syncthreads();     // Ps + Vs visible
        // PV: ctx^T += V^T x P^T over k=128
        #pragma unroll
        for (int ks = 0; ks < 128; ks += 8) {
            uint32_t af[4], bf[4][2];
            int a0 = (ks + ct) * 72 + pm + g;
            af[0] = __float_as_uint(Vsf[a0]);       af[1] = __float_as_uint(Vsf[a0 + 8]);
            af[2] = __float_as_uint(Vsf[a0 + 288]); af[3] = __float_as_uint(Vsf[a0 + 296]);
            #pragma unroll
            for (int j = 0; j < 4; j++) {
                int b0 = (pn + j * 8 + g) * 132 + ks + ct;
                bf[j][0] = Ps[b0]; bf[j][1] = Ps[b0 + 4];
            }
            #pragma unroll
            for (int j = 0; j < 4; j++) mma8(d[j], af, bf[j]);
        }
    }
    __syncthreads();
    // stage ctx^T -> smem (float, stride 68), tf32-rounded for oproj
    float* ctxs = (float*)Ps;
    {
        int dh = pm + g;
        #pragma unroll
        for (int j = 0; j < 4; j++) {
            int qq = pn + j * 8 + ct * 2;
            ctxs[qq * 68 + dh]           = __uint_as_float(tf32c(d[j][0]));
            ctxs[(qq + 1) * 68 + dh]     = __uint_as_float(tf32c(d[j][1]));
            ctxs[qq * 68 + dh + 8]       = __uint_as_float(tf32c(d[j][2]));
            ctxs[(qq + 1) * 68 + dh + 8] = __uint_as_float(tf32c(d[j][3]));
        }
    }
    __syncthreads();
    float* C = g_ctx + (size_t)bh * SS * DH + (size_t)q0 * DH;
    #pragma unroll
    for (int it = 0; it < 4; it++) {
        int fi = tid + it * 512;
        int r = fi >> 4, c4 = (fi & 15) << 2;
        *(float4*)(C + (size_t)r * DH + c4) = *(float4*)&ctxs[r * 68 + c4];
    }
}

// ---------------------------------------------------------------------------
// K4: output projection. ctx pre-rounded tf32 -> no A-side cvt.
// ---------------------------------------------------------------------------
__global__ __launch_bounds__(256, 2) void k_oproj(
    const float* __restrict__ wo, const float* __restrict__ bo, float* __restrict__ out)
{
    __shared__ float As[2][2560];
    __shared__ float Bs[2][2560];
    int tid = threadIdx.x;
    int lane = tid & 31, wid = tid >> 5;
    int g = lane >> 2, ct = lane & 3;
    int mb = (wid >> 2) * 64, nb = (wid & 3) * 32;
    int m0 = blockIdx.y * 128, n0 = blockIdx.x * 128;

    uint32_t asb = (uint32_t)__cvta_generic_to_shared(&As[0][0]);
    uint32_t bsb = (uint32_t)__cvta_generic_to_shared(&Bs[0][0]);
    int rl = tid >> 2, cl = (tid & 3) << 2;

    int m_a = m0 + rl,        b_a = m_a >> 11, s_a = m_a & (SS - 1);
    int m_b = m0 + rl + 64,   b_b = m_b >> 11, s_b = m_b & (SS - 1);

    float c[4][4][4];
    #pragma unroll
    for (int i = 0; i < 4; i++)
        #pragma unroll
        for (int j = 0; j < 4; j++)
            #pragma unroll
            for (int t = 0; t < 4; t++) c[i][j][t] = 0.0f;

    {
        int h = cl >> 6, dh = cl & 63;
        cpa16(asb + (0 * 2560 + rl * 20 + cl) * 4,
              g_ctx + ((size_t)(b_a * HH + h) * SS + s_a) * DH + dh);
        cpa16(asb + (0 * 2560 + (rl + 64) * 20 + cl) * 4,
              g_ctx + ((size_t)(b_b * HH + h) * SS + s_b) * DH + dh);
        cpa16(bsb + (0 * 2560 + rl * 20 + cl) * 4,        wo + (size_t)(n0 + rl) * DM + cl);
        cpa16(bsb + (0 * 2560 + (rl + 64) * 20 + cl) * 4, wo + (size_t)(n0 + rl + 64) * DM + cl);
    }
    CP_COMMIT;

    for (int k0 = 0, st = 0; k0 < DM; k0 += 16, st ^= 1) {
        CP_WAIT0;
        __syncthreads();
        if (k0 + 16 < DM) {
            int kn = k0 + 16, so = (st ^ 1) * 2560;
            int kidx = kn + cl;
            int h = kidx >> 6, dh = kidx & 63;
            cpa16(asb + (so + rl * 20 + cl) * 4,
                  g_ctx + ((size_t)(b_a * HH + h) * SS + s_a) * DH + dh);
            cpa16(asb + (so + (rl + 64) * 20 + cl) * 4,
                  g_ctx + ((size_t)(b_b * HH + h) * SS + s_b) * DH + dh);
            cpa16(bsb + (so + rl * 20 + cl) * 4,        wo + (size_t)(n0 + rl) * DM + kn + cl);
            cpa16(bsb + (so + (rl + 64) * 20 + cl) * 4, wo + (size_t)(n0 + rl + 64) * DM + kn + cl);
        }
        CP_COMMIT;
        const float* Af = &As[st][0];
        const float* Bf = &Bs[st][0];
        #pragma unroll
        for (int ks = 0; ks < 16; ks += 8) {
            uint32_t af[4][4], bf[4][2];
            #pragma unroll
            for (int i = 0; i < 4; i++) {
                int r0 = (mb + i * 16 + g) * 20 + ks + ct;
                af[i][0] = __float_as_uint(Af[r0]);       af[i][2] = __float_as_uint(Af[r0 + 4]);
                af[i][1] = __float_as_uint(Af[r0 + 160]); af[i][3] = __float_as_uint(Af[r0 + 164]);
            }
            #pragma unroll
            for (int j = 0; j < 4; j++) {
                int b0 = (nb + j * 8 + g) * 20 + ks + ct;
                bf[j][0] = tf32c(Bf[b0]); bf[j][1] = tf32c(Bf[b0 + 4]);
            }
            #pragma unroll
            for (int i = 0; i < 4; i++)
                #pragma unroll
                for (int j = 0; j < 4; j++) mma8(c[i][j], af[i], bf[j]);
        }
    }
    __syncthreads();
    #pragma unroll
    for (int i = 0; i < 4; i++) {
        int row = m0 + mb + i * 16 + g;
        #pragma unroll
        for (int j = 0; j < 4; j++) {
            int col = n0 + nb + j * 8 + ct * 2;
            float2 bi = *(const float2*)&bo[col];
            *(float2*)&out[(size_t)row * DM + col] =
                make_float2(c[i][j][0] + bi.x, c[i][j][1] + bi.y);
            *(float2*)&out[(size_t)(row + 8) * DM + col] =
                make_float2(c[i][j][2] + bi.x, c[i][j][3] + bi.y);
        }
    }
}

// ---------------------------------------------------------------------------
extern "C" void kernel_launch(void* const* d_in, const int* in_sizes, int n_in,
                              void* d_out, int out_size)
{
    const float* q    = (const float*)d_in[0];
    const float* k    = (const float*)d_in[1];
    const float* v    = (const float*)d_in[2];
    const float* mask = (const float*)d_in[3];
    const float* w_q  = (const float*)d_in[4];
    const float* b_q  = (const float*)d_in[5];
    const float* w_k  = (const float*)d_in[6];
    const float* b_k  = (const float*)d_in[7];
    const float* w_v  = (const float*)d_in[8];
    const float* b_v  = (const float*)d_in[9];
    const float* w_o  = (const float*)d_in[10];
    const float* b_o  = (const float*)d_in[11];

    float* out   = (float*)d_out;                        // x: [B,S,DM]
    float* score = out + (size_t)BB * SS * DM;           // score: [B,H,S,S]

    cudaFuncSetAttribute(k_attn, cudaFuncAttributeMaxDynamicSharedMemorySize, AT_BYTES);

    k_qkv_proj<<<dim3(DM/128, (BB*SS)/128, 3), 256>>>(q, k, v, w_q, w_k, w_v, b_q, b_k, b_v);
    k_attn<<<dim3(SS/128, BHT), 512, AT_BYTES>>>(mask, score);
    k_oproj<<<dim3(DM/128, (BB*SS)/128), 256>>>(w_o, b_o, out);
}

// round 10
// speedup vs baseline: 1.5039x; 1.5039x over previous
#include <cuda_runtime.h>
#include <cuda_fp16.h>
#include <cstdint>

// Problem constants
#define BB   4
#define SS   2048
#define HH   16
#define DH   64
#define DM   1024
#define BHT  (BB*HH)          // 64
#define NX   (BB*SS*DM)       // 8388608
#define NW   (DM*DM)          // 1048576
#define NH   ((size_t)BB*HH*SS*DH)

// Scratch (device globals, fp16)
__device__ __half g_xh0[NX], g_xh1[NX], g_xh2[NX];          // fp16 inputs
__device__ __half g_wh0[NW], g_wh1[NW], g_wh2[NW], g_wh3[NW]; // fp16 weights
__device__ __half g_qh[NH], g_kh[NH];                       // [bh][s][dh]
__device__ __half g_vt[NH];                                 // [bh][dh][s]  (V^T)
__device__ __half g_ctx[NH];                                // [bh][s][dh]

// ---------------------------------------------------------------------------
// helpers
// ---------------------------------------------------------------------------
__device__ __forceinline__ void mma16(float c[4], const uint32_t a[4], const uint32_t b[2]) {
    asm volatile(
        "mma.sync.aligned.m16n8k16.row.col.f32.f16.f16.f32 "
        "{%0,%1,%2,%3},{%4,%5,%6,%7},{%8,%9},{%0,%1,%2,%3};"
        : "+f"(c[0]), "+f"(c[1]), "+f"(c[2]), "+f"(c[3])
        : "r"(a[0]), "r"(a[1]), "r"(a[2]), "r"(a[3]), "r"(b[0]), "r"(b[1]));
}
__device__ __forceinline__ float fexp(float x) {
    float y = x * 1.4426950408889634f;
    float r = rintf(y);
    float c = (y - r) * 0.6931471805599453f;
    float p = 1.3888889e-3f;
    p = fmaf(p, c, 8.3333333e-3f);
    p = fmaf(p, c, 4.1666667e-2f);
    p = fmaf(p, c, 1.6666667e-1f);
    p = fmaf(p, c, 0.5f);
    p = fmaf(p, c, 1.0f);
    p = fmaf(p, c, 1.0f);
    return p * __int_as_float(((int)r + 127) << 23);
}
__device__ __forceinline__ void cpa16(uint32_t saddr, const void* g) {
    asm volatile("cp.async.ca.shared.global [%0], [%1], 16;" :: "r"(saddr), "l"(g));
}
#define CP_COMMIT asm volatile("cp.async.commit_group;")
#define CP_WAIT0  asm volatile("cp.async.wait_group 0;")
#define CP_WAIT1  asm volatile("cp.async.wait_group 1;")
__device__ __forceinline__ uint32_t h2u(__half2 h) { return *(uint32_t*)&h; }

// ---------------------------------------------------------------------------
// K0: convert inputs + weights to fp16
// ---------------------------------------------------------------------------
__global__ void k_prep(const float* __restrict__ q, const float* __restrict__ k,
                       const float* __restrict__ v, const float* __restrict__ wq,
                       const float* __restrict__ wk, const float* __restrict__ wv,
                       const float* __restrict__ wo)
{
    int z = blockIdx.z;
    size_t i4 = (size_t)blockIdx.x * blockDim.x + threadIdx.x;
    const float4* src; __half* dst; size_t n4;
    switch (z) {
        case 0: src = (const float4*)q;  dst = g_xh0; n4 = NX / 4; break;
        case 1: src = (const float4*)k;  dst = g_xh1; n4 = NX / 4; break;
        case 2: src = (const float4*)v;  dst = g_xh2; n4 = NX / 4; break;
        case 3: src = (const float4*)wq; dst = g_wh0; n4 = NW / 4; break;
        case 4: src = (const float4*)wk; dst = g_wh1; n4 = NW / 4; break;
        case 5: src = (const float4*)wv; dst = g_wh2; n4 = NW / 4; break;
        default: src = (const float4*)wo; dst = g_wh3; n4 = NW / 4; break;
    }
    if (i4 < n4) {
        float4 a = src[i4];
        __half2 lo = __floats2half2_rn(a.x, a.y);
        __half2 hi = __floats2half2_rn(a.z, a.w);
        uint2 w = make_uint2(h2u(lo), h2u(hi));
        *(uint2*)&dst[i4 * 4] = w;
    }
}

// ---------------------------------------------------------------------------
// K1: fused QKV projection, fp16 m16n8k16. 128x128 tile, 64x32 warp tiles,
// BK=32 (2 k16 chunks), cp.async double buffer. Smem stores half2 pairs
// (uint32) with row stride 20 words (16 kpairs + 4 pad, conflict-free).
// z==2 writes V TRANSPOSED (g_vt[bh][dh][s]).
// ---------------------------------------------------------------------------
__global__ __launch_bounds__(256, 2) void k_qkv_proj(
    const float* __restrict__ bq, const float* __restrict__ bk,
    const float* __restrict__ bv)
{
    __shared__ uint32_t As[2][2560];
    __shared__ uint32_t Bs[2][2560];
    int z = blockIdx.z;
    const __half* X  = (z == 0) ? g_xh0 : (z == 1) ? g_xh1 : g_xh2;
    const __half* W  = (z == 0) ? g_wh0 : (z == 1) ? g_wh1 : g_wh2;
    const float*  Bi = (z == 0) ? bq : (z == 1) ? bk : bv;

    int tid = threadIdx.x;
    int lane = tid & 31, wid = tid >> 5;
    int g = lane >> 2, ct = lane & 3;
    int mb = (wid >> 2) * 64, nb = (wid & 3) * 32;
    int m0 = blockIdx.y * 128, n0 = blockIdx.x * 128;

    uint32_t asb = (uint32_t)__cvta_generic_to_shared(&As[0][0]);
    uint32_t bsb = (uint32_t)__cvta_generic_to_shared(&Bs[0][0]);

    float c[4][4][4];
    #pragma unroll
    for (int i = 0; i < 4; i++)
        #pragma unroll
        for (int j = 0; j < 4; j++)
            #pragma unroll
            for (int t = 0; t < 4; t++) c[i][j][t] = 0.0f;

    // loader: 128 rows x 32 halfs (64B) per operand = 512 slots of 16B; 2/thread
    #define QLOAD(st_, k0_) do {                                                \
        _Pragma("unroll")                                                       \
        for (int it = 0; it < 2; it++) {                                        \
            int sl = tid + it * 256;                                            \
            int r = sl >> 2, ch = sl & 3;                                       \
            cpa16(asb + ((st_) * 2560 + r * 20 + ch * 4) * 4,                   \
                  X + (size_t)(m0 + r) * DM + (k0_) + ch * 8);                  \
            cpa16(bsb + ((st_) * 2560 + r * 20 + ch * 4) * 4,                   \
                  W + (size_t)(n0 + r) * DM + (k0_) + ch * 8);                  \
        }                                                                       \
    } while (0)

    QLOAD(0, 0);
    CP_COMMIT;

    for (int k0 = 0, st = 0; k0 < DM; k0 += 32, st ^= 1) {
        CP_WAIT0;
        __syncthreads();
        if (k0 + 32 < DM) QLOAD(st ^ 1, k0 + 32);
        CP_COMMIT;
        const uint32_t* Af = &As[st][0];
        const uint32_t* Bf = &Bs[st][0];
        #pragma unroll
        for (int kc = 0; kc < 2; kc++) {
            uint32_t af[4][4], bf[4][2];
            #pragma unroll
            for (int i = 0; i < 4; i++) {
                int r0 = (mb + i * 16 + g) * 20 + kc * 8 + ct;
                af[i][0] = Af[r0];       af[i][1] = Af[r0 + 160];
                af[i][2] = Af[r0 + 4];   af[i][3] = Af[r0 + 164];
            }
            #pragma unroll
            for (int j = 0; j < 4; j++) {
                int b0 = (nb + j * 8 + g) * 20 + kc * 8 + ct;
                bf[j][0] = Bf[b0]; bf[j][1] = Bf[b0 + 4];
            }
            #pragma unroll
            for (int i = 0; i < 4; i++)
                #pragma unroll
                for (int j = 0; j < 4; j++) mma16(c[i][j], af[i], bf[j]);
        }
    }
    #undef QLOAD
    __syncthreads();
    // epilogue
    #pragma unroll
    for (int i = 0; i < 4; i++) {
        int row = m0 + mb + i * 16 + g;
        int b_ = row >> 11, s_ = row & (SS - 1);
        #pragma unroll
        for (int j = 0; j < 4; j++) {
            int col = n0 + nb + j * 8 + ct * 2;
            int h = col >> 6, dh = col & 63;
            float2 bi = *(const float2*)&Bi[col];
            float v0 = c[i][j][0] + bi.x, v1 = c[i][j][1] + bi.y;
            float v2 = c[i][j][2] + bi.x, v3 = c[i][j][3] + bi.y;
            if (z == 2) {
                size_t tb = ((size_t)(b_ * HH + h) * DH + dh) * SS;
                g_vt[tb + s_]            = __float2half_rn(v0);
                g_vt[tb + SS + s_]       = __float2half_rn(v1);
                g_vt[tb + s_ + 8]        = __float2half_rn(v2);
                g_vt[tb + SS + s_ + 8]   = __float2half_rn(v3);
            } else {
                __half* O = (z == 0) ? g_qh : g_kh;
                size_t base = ((size_t)(b_ * HH + h) * SS + s_) * DH + dh;
                *(uint32_t*)&O[base]          = h2u(__floats2half2_rn(v0, v1));
                *(uint32_t*)&O[base + 8 * DH] = h2u(__floats2half2_rn(v2, v3));
            }
        }
    }
}

// ---------------------------------------------------------------------------
// K2: fused attention, fp16. 256 threads, QK warp tile 32q x 64n (4m x 2n),
// PV via register-reuse of QK C-fragments as A + V^T smem as B. No Ps smem.
// smem words: Qs[128*36]@0 | Ks 2x[128*36]@4608 | Vt[64*68]@13824 |
//             redc f32[128*68]@18176 | rowp[256]@26880 | invs[128]@27136
// ---------------------------------------------------------------------------
#define AQ  0
#define AK  4608
#define AV  13824
#define ARD 18176
#define ARP 26880
#define AIV 27136
#define AT_WORDS 27264
#define AT_BYTES (AT_WORDS * 4)

__global__ __launch_bounds__(256, 1) void k_attn(
    const float* __restrict__ mask, float* __restrict__ score)
{
    extern __shared__ uint32_t sm[];
    uint32_t* Qs = sm + AQ;
    uint32_t* Vt = sm + AV;
    float* redc  = (float*)(sm + ARD);
    float* rowp  = (float*)(sm + ARP);
    float* invs  = (float*)(sm + AIV);
    uint32_t smb = (uint32_t)__cvta_generic_to_shared(sm);

    int bh = blockIdx.y, q0 = blockIdx.x * 128;
    const __half* Q = g_qh + (size_t)bh * SS * DH;
    const __half* K = g_kh + (size_t)bh * SS * DH;
    const __half* V = g_vt + (size_t)bh * DH * SS;   // [dh][s]

    int tid = threadIdx.x, lane = tid & 31, wid = tid >> 5;
    int g = lane >> 2, ct = lane & 3;
    int mb = (wid & 3) * 32;      // q strip (32 rows)
    int nw = wid >> 2;            // n strip 0/1 (64 cols)
    int nb = nw * 64;

    // Q tile -> smem (1024 x 16B slots? 128 rows x 8 chunks = 1024; 4/thread)
    #pragma unroll
    for (int it = 0; it < 4; it++) {
        int sl = tid + it * 256;
        int r = sl >> 3, ch = sl & 7;
        cpa16(smb + (AQ + r * 36 + ch * 4) * 4, Q + (size_t)(q0 + r) * DH + ch * 8);
    }

    #define KLOAD(st_, n0_) do {                                                \
        _Pragma("unroll")                                                       \
        for (int it = 0; it < 4; it++) {                                        \
            int sl = tid + it * 256;                                            \
            int r = sl >> 3, ch = sl & 7;                                       \
            cpa16(smb + (AK + (st_) * 4608 + r * 36 + ch * 4) * 4,              \
                  K + (size_t)((n0_) + r) * DH + ch * 8);                       \
        }                                                                       \
    } while (0)
    #define VLOAD(n0_) do {                                                     \
        _Pragma("unroll")                                                       \
        for (int it = 0; it < 4; it++) {                                        \
            int sl = tid + it * 256;                                            \
            int r = sl >> 4, ch = sl & 15;                                      \
            cpa16(smb + (AV + r * 68 + ch * 4) * 4,                             \
                  V + (size_t)r * SS + (n0_) + ch * 8);                         \
        }                                                                       \
    } while (0)

    float c[2][8][4];
    float rs[2][2];
    #pragma unroll
    for (int i = 0; i < 2; i++) { rs[i][0] = 0.0f; rs[i][1] = 0.0f; }

    // ---------------- Pass A: row sums ----------------
    KLOAD(0, 0);
    CP_COMMIT;
    for (int n0 = 0, st = 0; n0 < SS; n0 += 128, st ^= 1) {
        CP_WAIT0;
        __syncthreads();
        if (n0 + 128 < SS) KLOAD(st ^ 1, n0 + 128);
        CP_COMMIT;
        const uint32_t* Kf = sm + AK + st * 4608;
        #pragma unroll
        for (int i = 0; i < 2; i++)
            #pragma unroll
            for (int j = 0; j < 8; j++)
                #pragma unroll
                for (int t = 0; t < 4; t++) c[i][j][t] = 0.0f;
        #pragma unroll
        for (int kc = 0; kc < 4; kc++) {
            uint32_t af[2][4], bf[8][2];
            #pragma unroll
            for (int i = 0; i < 2; i++) {
                int r0 = (mb + i * 16 + g) * 36 + kc * 8 + ct;
                af[i][0] = Qs[r0];     af[i][1] = Qs[r0 + 288];
                af[i][2] = Qs[r0 + 4]; af[i][3] = Qs[r0 + 292];
            }
            #pragma unroll
            for (int j = 0; j < 8; j++) {
                int b0 = (nb + j * 8 + g) * 36 + kc * 8 + ct;
                bf[j][0] = Kf[b0]; bf[j][1] = Kf[b0 + 4];
            }
            #pragma unroll
            for (int i = 0; i < 2; i++)
                #pragma unroll
                for (int j = 0; j < 8; j++) mma16(c[i][j], af[i], bf[j]);
        }
        #pragma unroll
        for (int i = 0; i < 2; i++) {
            int row = q0 + mb + i * 16 + g;
            #pragma unroll
            for (int j = 0; j < 8; j++) {
                int colg = n0 + nb + j * 8 + ct * 2;
                float2 mk0 = *(const float2*)&mask[(size_t)row * SS + colg];
                rs[i][0] += fexp(fmaf(c[i][j][0], 0.125f, mk0.x))
                          + fexp(fmaf(c[i][j][1], 0.125f, mk0.y));
                float2 mk1 = *(const float2*)&mask[(size_t)(row + 8) * SS + colg];
                rs[i][1] += fexp(fmaf(c[i][j][2], 0.125f, mk1.x))
                          + fexp(fmaf(c[i][j][3], 0.125f, mk1.y));
            }
        }
    }
    #pragma unroll
    for (int i = 0; i < 2; i++) {
        #pragma unroll
        for (int hh = 0; hh < 2; hh++) {
            float v = rs[i][hh];
            v += __shfl_xor_sync(0xffffffff, v, 1);
            v += __shfl_xor_sync(0xffffffff, v, 2);
            if (ct == 0) rowp[(mb + i * 16 + hh * 8 + g) * 2 + nw] = v;
        }
    }
    __syncthreads();
    if (tid < 128) invs[tid] = 1.0f / (rowp[tid * 2] + rowp[tid * 2 + 1]);

    // ---------------- Pass B: score + ctx ----------------
    float d[2][8][4];
    #pragma unroll
    for (int i = 0; i < 2; i++)
        #pragma unroll
        for (int j = 0; j < 8; j++)
            #pragma unroll
            for (int t = 0; t < 4; t++) d[i][j][t] = 0.0f;

    size_t sbase = (size_t)bh * SS * SS;

    KLOAD(0, 0);
    CP_COMMIT;
    for (int n0 = 0, st = 0; n0 < SS; n0 += 128, st ^= 1) {
        CP_WAIT0;            // K_cur ready (+ everything older)
        __syncthreads();     // prev PV readers of Vt done; invs visible (iter 0)
        VLOAD(n0);
        CP_COMMIT;
        if (n0 + 128 < SS) KLOAD(st ^ 1, n0 + 128);
        CP_COMMIT;

        const uint32_t* Kf = sm + AK + st * 4608;
        #pragma unroll
        for (int i = 0; i < 2; i++)
            #pragma unroll
            for (int j = 0; j < 8; j++)
                #pragma unroll
                for (int t = 0; t < 4; t++) c[i][j][t] = 0.0f;
        #pragma unroll
        for (int kc = 0; kc < 4; kc++) {
            uint32_t af[2][4], bf[8][2];
            #pragma unroll
            for (int i = 0; i < 2; i++) {
                int r0 = (mb + i * 16 + g) * 36 + kc * 8 + ct;
                af[i][0] = Qs[r0];     af[i][1] = Qs[r0 + 288];
                af[i][2] = Qs[r0 + 4]; af[i][3] = Qs[r0 + 292];
            }
            #pragma unroll
            for (int j = 0; j < 8; j++) {
                int b0 = (nb + j * 8 + g) * 36 + kc * 8 + ct;
                bf[j][0] = Kf[b0]; bf[j][1] = Kf[b0 + 4];
            }
            #pragma unroll
            for (int i = 0; i < 2; i++)
                #pragma unroll
                for (int j = 0; j < 8; j++) mma16(c[i][j], af[i], bf[j]);
        }
        // epilogue: p -> score (fp32) + pack fp16 A-fragments in registers
        uint32_t plo[2][8], phi[2][8];
        #pragma unroll
        for (int i = 0; i < 2; i++) {
            int rloc = mb + i * 16 + g;
            float iv0 = invs[rloc], iv1 = invs[rloc + 8];
            int grow = q0 + rloc;
            #pragma unroll
            for (int j = 0; j < 8; j++) {
                int colg = n0 + nb + j * 8 + ct * 2;
                float2 mk0 = *(const float2*)&mask[(size_t)grow * SS + colg];
                float p0 = fexp(fmaf(c[i][j][0], 0.125f, mk0.x)) * iv0;
                float p1 = fexp(fmaf(c[i][j][1], 0.125f, mk0.y)) * iv0;
                *(float2*)&score[sbase + (size_t)grow * SS + colg] = make_float2(p0, p1);
                float2 mk1 = *(const float2*)&mask[(size_t)(grow + 8) * SS + colg];
                float p2 = fexp(fmaf(c[i][j][2], 0.125f, mk1.x)) * iv1;
                float p3 = fexp(fmaf(c[i][j][3], 0.125f, mk1.y)) * iv1;
                *(float2*)&score[sbase + (size_t)(grow + 8) * SS + colg] = make_float2(p2, p3);
                plo[i][j] = h2u(__floats2half2_rn(p0, p1));
                phi[i][j] = h2u(__floats2half2_rn(p2, p3));
            }
        }
        CP_WAIT1;            // Vt done (K_next may remain in flight)
        __syncthreads();     // Vt visible to all
        // PV: ctx += P @ V ; A = packed p regs, B = V^T smem (plain LDS)
        #pragma unroll
        for (int jj = 0; jj < 4; jj++) {
            uint32_t bf[8][2];
            #pragma unroll
            for (int jd = 0; jd < 8; jd++) {
                int b0 = (jd * 8 + g) * 68 + nw * 32 + jj * 8 + ct;
                bf[jd][0] = Vt[b0]; bf[jd][1] = Vt[b0 + 4];
            }
            #pragma unroll
            for (int i = 0; i < 2; i++) {
                uint32_t pa[4] = { plo[i][2 * jj], phi[i][2 * jj],
                                   plo[i][2 * jj + 1], phi[i][2 * jj + 1] };
                #pragma unroll
                for (int jd = 0; jd < 8; jd++) mma16(d[i][jd], pa, bf[jd]);
            }
        }
    }
    #undef KLOAD
    #undef VLOAD
    __syncthreads();
    // ctx reduction across the 2 n-strip warps, then store fp16 ctx
    if (nw == 1) {
        #pragma unroll
        for (int i = 0; i < 2; i++) {
            int r0 = mb + i * 16 + g;
            #pragma unroll
            for (int jd = 0; jd < 8; jd++) {
                int col = jd * 8 + ct * 2;
                redc[r0 * 68 + col]           = d[i][jd][0];
                redc[r0 * 68 + col + 1]       = d[i][jd][1];
                redc[(r0 + 8) * 68 + col]     = d[i][jd][2];
                redc[(r0 + 8) * 68 + col + 1] = d[i][jd][3];
            }
        }
    }
    __syncthreads();
    if (nw == 0) {
        #pragma unroll
        for (int i = 0; i < 2; i++) {
            int r0 = mb + i * 16 + g;
            #pragma unroll
            for (int jd = 0; jd < 8; jd++) {
                int col = jd * 8 + ct * 2;
                float v0 = d[i][jd][0] + redc[r0 * 68 + col];
                float v1 = d[i][jd][1] + redc[r0 * 68 + col + 1];
                float v2 = d[i][jd][2] + redc[(r0 + 8) * 68 + col];
                float v3 = d[i][jd][3] + redc[(r0 + 8) * 68 + col + 1];
                size_t b0 = ((size_t)bh * SS + q0 + r0) * DH + col;
                *(uint32_t*)&g_ctx[b0]          = h2u(__floats2half2_rn(v0, v1));
                *(uint32_t*)&g_ctx[b0 + 8 * DH] = h2u(__floats2half2_rn(v2, v3));
            }
        }
    }
}

// ---------------------------------------------------------------------------
// K4: output projection, fp16. A = g_ctx (gathered across heads), B = g_wh3.
// ---------------------------------------------------------------------------
__global__ __launch_bounds__(256, 2) void k_oproj(
    const float* __restrict__ bo, float* __restrict__ out)
{
    __shared__ uint32_t As[2][2560];
    __shared__ uint32_t Bs[2][2560];
    int tid = threadIdx.x;
    int lane = tid & 31, wid = tid >> 5;
    int g = lane >> 2, ct = lane & 3;
    int mb = (wid >> 2) * 64, nb = (wid & 3) * 32;
    int m0 = blockIdx.y * 128, n0 = blockIdx.x * 128;

    uint32_t asb = (uint32_t)__cvta_generic_to_shared(&As[0][0]);
    uint32_t bsb = (uint32_t)__cvta_generic_to_shared(&Bs[0][0]);

    float c[4][4][4];
    #pragma unroll
    for (int i = 0; i < 4; i++)
        #pragma unroll
        for (int j = 0; j < 4; j++)
            #pragma unroll
            for (int t = 0; t < 4; t++) c[i][j][t] = 0.0f;

    #define OLOAD(st_, k0_) do {                                                \
        _Pragma("unroll")                                                       \
        for (int it = 0; it < 2; it++) {                                        \
            int sl = tid + it * 256;                                            \
            int r = sl >> 2, ch = sl & 3;                                       \
            int m = m0 + r;                                                     \
            int b_ = m >> 11, s_ = m & (SS - 1);                                \
            int kk = (k0_) + ch * 8;                                            \
            int h = kk >> 6, dhh = kk & 63;                                     \
            cpa16(asb + ((st_) * 2560 + r * 20 + ch * 4) * 4,                   \
                  g_ctx + ((size_t)(b_ * HH + h) * SS + s_) * DH + dhh);        \
            cpa16(bsb + ((st_) * 2560 + r * 20 + ch * 4) * 4,                   \
                  g_wh3 + (size_t)(n0 + r) * DM + (k0_) + ch * 8);              \
        }                                                                       \
    } while (0)

    OLOAD(0, 0);
    CP_COMMIT;

    for (int k0 = 0, st = 0; k0 < DM; k0 += 32, st ^= 1) {
        CP_WAIT0;
        __syncthreads();
        if (k0 + 32 < DM) OLOAD(st ^ 1, k0 + 32);
        CP_COMMIT;
        const uint32_t* Af = &As[st][0];
        const uint32_t* Bf = &Bs[st][0];
        #pragma unroll
        for (int kc = 0; kc < 2; kc++) {
            uint32_t af[4][4], bf[4][2];
            #pragma unroll
            for (int i = 0; i < 4; i++) {
                int r0 = (mb + i * 16 + g) * 20 + kc * 8 + ct;
                af[i][0] = Af[r0];     af[i][1] = Af[r0 + 160];
                af[i][2] = Af[r0 + 4]; af[i][3] = Af[r0 + 164];
            }
            #pragma unroll
            for (int j = 0; j < 4; j++) {
                int b0 = (nb + j * 8 + g) * 20 + kc * 8 + ct;
                bf[j][0] = Bf[b0]; bf[j][1] = Bf[b0 + 4];
            }
            #pragma unroll
            for (int i = 0; i < 4; i++)
                #pragma unroll
                for (int j = 0; j < 4; j++) mma16(c[i][j], af[i], bf[j]);
        }
    }
    #undef OLOAD
    __syncthreads();
    #pragma unroll
    for (int i = 0; i < 4; i++) {
        int row = m0 + mb + i * 16 + g;
        #pragma unroll
        for (int j = 0; j < 4; j++) {
            int col = n0 + nb + j * 8 + ct * 2;
            float2 bi = *(const float2*)&bo[col];
            *(float2*)&out[(size_t)row * DM + col] =
                make_float2(c[i][j][0] + bi.x, c[i][j][1] + bi.y);
            *(float2*)&out[(size_t)(row + 8) * DM + col] =
                make_float2(c[i][j][2] + bi.x, c[i][j][3] + bi.y);
        }
    }
}

// ---------------------------------------------------------------------------
extern "C" void kernel_launch(void* const* d_in, const int* in_sizes, int n_in,
                              void* d_out, int out_size)
{
    const float* q    = (const float*)d_in[0];
    const float* k    = (const float*)d_in[1];
    const float* v    = (const float*)d_in[2];
    const float* mask = (const float*)d_in[3];
    const float* b_q  = (const float*)d_in[5];
    const float* w_q  = (const float*)d_in[4];
    const float* w_k  = (const float*)d_in[6];
    const float* b_k  = (const float*)d_in[7];
    const float* w_v  = (const float*)d_in[8];
    const float* b_v  = (const float*)d_in[9];
    const float* w_o  = (const float*)d_in[10];
    const float* b_o  = (const float*)d_in[11];

    float* out   = (float*)d_out;                        // x: [B,S,DM]
    float* score = out + (size_t)BB * SS * DM;           // score: [B,H,S,S]

    cudaFuncSetAttribute(k_attn, cudaFuncAttributeMaxDynamicSharedMemorySize, AT_BYTES);

    k_prep<<<dim3(4096, 1, 7), 512>>>(q, k, v, w_q, w_k, w_v, w_o);
    k_qkv_proj<<<dim3(DM/128, (BB*SS)/128, 3), 256>>>(b_q, b_k, b_v);
    k_attn<<<dim3(SS/128, BHT), 256, AT_BYTES>>>(mask, score);
    k_oproj<<<dim3(DM/128, (BB*SS)/128), 256>>>(b_o, out);
}

// round 11
// speedup vs baseline: 1.6173x; 1.0754x over previous
#include <cuda_runtime.h>
#include <cuda_fp16.h>
#include <cstdint>

// Problem constants
#define BB   4
#define SS   2048
#define HH   16
#define DH   64
#define DM   1024
#define BHT  (BB*HH)          // 64
#define NX   (BB*SS*DM)       // 8388608
#define NW   (DM*DM)          // 1048576
#define NH   ((size_t)BB*HH*SS*DH)

// Scratch (device globals, fp16)
__device__ __half g_xh0[NX], g_xh1[NX], g_xh2[NX];            // fp16 inputs
__device__ __half g_wh0[NW], g_wh1[NW], g_wh2[NW], g_wh3[NW]; // fp16 weights
__device__ __half g_qh[NH], g_kh[NH];                         // [bh][s][dh]
__device__ __half g_vt[NH];                                   // [bh][dh][s]  (V^T)
__device__ __half g_ctx[NH];                                  // [bh][s][dh]

// ---------------------------------------------------------------------------
// helpers
// ---------------------------------------------------------------------------
__device__ __forceinline__ void mma16(float c[4], const uint32_t a[4], const uint32_t b[2]) {
    asm volatile(
        "mma.sync.aligned.m16n8k16.row.col.f32.f16.f16.f32 "
        "{%0,%1,%2,%3},{%4,%5,%6,%7},{%8,%9},{%0,%1,%2,%3};"
        : "+f"(c[0]), "+f"(c[1]), "+f"(c[2]), "+f"(c[3])
        : "r"(a[0]), "r"(a[1]), "r"(a[2]), "r"(a[3]), "r"(b[0]), "r"(b[1]));
}
__device__ __forceinline__ float fexp(float x) {
    float y = x * 1.4426950408889634f;
    float r = rintf(y);
    float c = (y - r) * 0.6931471805599453f;
    float p = 1.3888889e-3f;
    p = fmaf(p, c, 8.3333333e-3f);
    p = fmaf(p, c, 4.1666667e-2f);
    p = fmaf(p, c, 1.6666667e-1f);
    p = fmaf(p, c, 0.5f);
    p = fmaf(p, c, 1.0f);
    p = fmaf(p, c, 1.0f);
    return p * __int_as_float(((int)r + 127) << 23);
}
__device__ __forceinline__ void cpa16(uint32_t saddr, const void* g) {
    asm volatile("cp.async.ca.shared.global [%0], [%1], 16;" :: "r"(saddr), "l"(g));
}
#define CP_COMMIT asm volatile("cp.async.commit_group;")
#define CP_WAIT0  asm volatile("cp.async.wait_group 0;")
#define CP_WAIT1  asm volatile("cp.async.wait_group 1;")
__device__ __forceinline__ uint32_t h2u(__half2 h) { return *(uint32_t*)&h; }

// ---------------------------------------------------------------------------
// K0: convert inputs + weights to fp16
// ---------------------------------------------------------------------------
__global__ void k_prep(const float* __restrict__ q, const float* __restrict__ k,
                       const float* __restrict__ v, const float* __restrict__ wq,
                       const float* __restrict__ wk, const float* __restrict__ wv,
                       const float* __restrict__ wo)
{
    int z = blockIdx.z;
    size_t i4 = (size_t)blockIdx.x * blockDim.x + threadIdx.x;
    const float4* src; __half* dst; size_t n4;
    switch (z) {
        case 0: src = (const float4*)q;  dst = g_xh0; n4 = NX / 4; break;
        case 1: src = (const float4*)k;  dst = g_xh1; n4 = NX / 4; break;
        case 2: src = (const float4*)v;  dst = g_xh2; n4 = NX / 4; break;
        case 3: src = (const float4*)wq; dst = g_wh0; n4 = NW / 4; break;
        case 4: src = (const float4*)wk; dst = g_wh1; n4 = NW / 4; break;
        case 5: src = (const float4*)wv; dst = g_wh2; n4 = NW / 4; break;
        default: src = (const float4*)wo; dst = g_wh3; n4 = NW / 4; break;
    }
    if (i4 < n4) {
        float4 a = src[i4];
        __half2 lo = __floats2half2_rn(a.x, a.y);
        __half2 hi = __floats2half2_rn(a.z, a.w);
        uint2 w = make_uint2(h2u(lo), h2u(hi));
        *(uint2*)&dst[i4 * 4] = w;
    }
}

// ---------------------------------------------------------------------------
// K1: fused QKV projection, fp16 m16n8k16. (unchanged from round 9)
// ---------------------------------------------------------------------------
__global__ __launch_bounds__(256, 2) void k_qkv_proj(
    const float* __restrict__ bq, const float* __restrict__ bk,
    const float* __restrict__ bv)
{
    __shared__ uint32_t As[2][2560];
    __shared__ uint32_t Bs[2][2560];
    int z = blockIdx.z;
    const __half* X  = (z == 0) ? g_xh0 : (z == 1) ? g_xh1 : g_xh2;
    const __half* W  = (z == 0) ? g_wh0 : (z == 1) ? g_wh1 : g_wh2;
    const float*  Bi = (z == 0) ? bq : (z == 1) ? bk : bv;

    int tid = threadIdx.x;
    int lane = tid & 31, wid = tid >> 5;
    int g = lane >> 2, ct = lane & 3;
    int mb = (wid >> 2) * 64, nb = (wid & 3) * 32;
    int m0 = blockIdx.y * 128, n0 = blockIdx.x * 128;

    uint32_t asb = (uint32_t)__cvta_generic_to_shared(&As[0][0]);
    uint32_t bsb = (uint32_t)__cvta_generic_to_shared(&Bs[0][0]);

    float c[4][4][4];
    #pragma unroll
    for (int i = 0; i < 4; i++)
        #pragma unroll
        for (int j = 0; j < 4; j++)
            #pragma unroll
            for (int t = 0; t < 4; t++) c[i][j][t] = 0.0f;

    #define QLOAD(st_, k0_) do {                                                \
        _Pragma("unroll")                                                       \
        for (int it = 0; it < 2; it++) {                                        \
            int sl = tid + it * 256;                                            \
            int r = sl >> 2, ch = sl & 3;                                       \
            cpa16(asb + ((st_) * 2560 + r * 20 + ch * 4) * 4,                   \
                  X + (size_t)(m0 + r) * DM + (k0_) + ch * 8);                  \
            cpa16(bsb + ((st_) * 2560 + r * 20 + ch * 4) * 4,                   \
                  W + (size_t)(n0 + r) * DM + (k0_) + ch * 8);                  \
        }                                                                       \
    } while (0)

    QLOAD(0, 0);
    CP_COMMIT;

    for (int k0 = 0, st = 0; k0 < DM; k0 += 32, st ^= 1) {
        CP_WAIT0;
        __syncthreads();
        if (k0 + 32 < DM) QLOAD(st ^ 1, k0 + 32);
        CP_COMMIT;
        const uint32_t* Af = &As[st][0];
        const uint32_t* Bf = &Bs[st][0];
        #pragma unroll
        for (int kc = 0; kc < 2; kc++) {
            uint32_t af[4][4], bf[4][2];
            #pragma unroll
            for (int i = 0; i < 4; i++) {
                int r0 = (mb + i * 16 + g) * 20 + kc * 8 + ct;
                af[i][0] = Af[r0];       af[i][1] = Af[r0 + 160];
                af[i][2] = Af[r0 + 4];   af[i][3] = Af[r0 + 164];
            }
            #pragma unroll
            for (int j = 0; j < 4; j++) {
                int b0 = (nb + j * 8 + g) * 20 + kc * 8 + ct;
                bf[j][0] = Bf[b0]; bf[j][1] = Bf[b0 + 4];
            }
            #pragma unroll
            for (int i = 0; i < 4; i++)
                #pragma unroll
                for (int j = 0; j < 4; j++) mma16(c[i][j], af[i], bf[j]);
        }
    }
    #undef QLOAD
    __syncthreads();
    #pragma unroll
    for (int i = 0; i < 4; i++) {
        int row = m0 + mb + i * 16 + g;
        int b_ = row >> 11, s_ = row & (SS - 1);
        #pragma unroll
        for (int j = 0; j < 4; j++) {
            int col = n0 + nb + j * 8 + ct * 2;
            int h = col >> 6, dh = col & 63;
            float2 bi = *(const float2*)&Bi[col];
            float v0 = c[i][j][0] + bi.x, v1 = c[i][j][1] + bi.y;
            float v2 = c[i][j][2] + bi.x, v3 = c[i][j][3] + bi.y;
            if (z == 2) {
                size_t tb = ((size_t)(b_ * HH + h) * DH + dh) * SS;
                g_vt[tb + s_]            = __float2half_rn(v0);
                g_vt[tb + SS + s_]       = __float2half_rn(v1);
                g_vt[tb + s_ + 8]        = __float2half_rn(v2);
                g_vt[tb + SS + s_ + 8]   = __float2half_rn(v3);
            } else {
                __half* O = (z == 0) ? g_qh : g_kh;
                size_t base = ((size_t)(b_ * HH + h) * SS + s_) * DH + dh;
                *(uint32_t*)&O[base]          = h2u(__floats2half2_rn(v0, v1));
                *(uint32_t*)&O[base + 8 * DH] = h2u(__floats2half2_rn(v2, v3));
            }
        }
    }
}

// ---------------------------------------------------------------------------
// K2: fused attention, fp16, 64-q-row CTA, 2 CTAs/SM for phase overlap.
// 8 warps: QK warp tile 16q x 64n (mb=(wid&3)*16, nw=wid>>2).
// PV via register-reuse of QK C-fragments; ctx reduced across the 2 n-strips.
// smem words: Qs[64*36]@0 | Ks 2x[128*36]@2304 | Vt[64*68]@11520 |
//             redc (overlay on Ks)@2304 | rowp[128]@15872 | invs[64]@16000
// ---------------------------------------------------------------------------
#define AQ  0
#define AK  2304
#define AV  11520
#define ARD AK
#define ARP 15872
#define AIV 16000
#define AT_WORDS 16064
#define AT_BYTES (AT_WORDS * 4)

__global__ __launch_bounds__(256, 2) void k_attn(
    const float* __restrict__ mask, float* __restrict__ score)
{
    extern __shared__ uint32_t sm[];
    uint32_t* Qs = sm + AQ;
    uint32_t* Vt = sm + AV;
    float* redc  = (float*)(sm + ARD);
    float* rowp  = (float*)(sm + ARP);
    float* invs  = (float*)(sm + AIV);
    uint32_t smb = (uint32_t)__cvta_generic_to_shared(sm);

    int bh = blockIdx.y, q0 = blockIdx.x * 64;
    const __half* Q = g_qh + (size_t)bh * SS * DH;
    const __half* K = g_kh + (size_t)bh * SS * DH;
    const __half* V = g_vt + (size_t)bh * DH * SS;   // [dh][s]

    int tid = threadIdx.x, lane = tid & 31, wid = tid >> 5;
    int g = lane >> 2, ct = lane & 3;
    int mb = (wid & 3) * 16;      // q strip (16 rows)
    int nw = wid >> 2;            // n strip 0/1 (64 cols)
    int nb = nw * 64;

    // Q tile -> smem: 64 rows x 8 chunks = 512 slots; 2/thread
    #pragma unroll
    for (int it = 0; it < 2; it++) {
        int sl = tid + it * 256;
        int r = sl >> 3, ch = sl & 7;
        cpa16(smb + (AQ + r * 36 + ch * 4) * 4, Q + (size_t)(q0 + r) * DH + ch * 8);
    }

    #define KLOAD(st_, n0_) do {                                                \
        _Pragma("unroll")                                                       \
        for (int it = 0; it < 4; it++) {                                        \
            int sl = tid + it * 256;                                            \
            int r = sl >> 3, ch = sl & 7;                                       \
            cpa16(smb + (AK + (st_) * 4608 + r * 36 + ch * 4) * 4,              \
                  K + (size_t)((n0_) + r) * DH + ch * 8);                       \
        }                                                                       \
    } while (0)
    #define VLOAD(n0_) do {                                                     \
        _Pragma("unroll")                                                       \
        for (int it = 0; it < 4; it++) {                                        \
            int sl = tid + it * 256;                                            \
            int r = sl >> 4, ch = sl & 15;                                      \
            cpa16(smb + (AV + r * 68 + ch * 4) * 4,                             \
                  V + (size_t)r * SS + (n0_) + ch * 8);                         \
        }                                                                       \
    } while (0)

    float c[8][4];
    float rs0 = 0.0f, rs1 = 0.0f;

    // ---------------- Pass A: row sums ----------------
    KLOAD(0, 0);
    CP_COMMIT;
    for (int n0 = 0, st = 0; n0 < SS; n0 += 128, st ^= 1) {
        CP_WAIT0;
        __syncthreads();
        if (n0 + 128 < SS) KLOAD(st ^ 1, n0 + 128);
        CP_COMMIT;
        const uint32_t* Kf = sm + AK + st * 4608;
        #pragma unroll
        for (int j = 0; j < 8; j++)
            #pragma unroll
            for (int t = 0; t < 4; t++) c[j][t] = 0.0f;
        #pragma unroll
        for (int kc = 0; kc < 4; kc++) {
            uint32_t af[4], bf[8][2];
            int r0 = (mb + g) * 36 + kc * 8 + ct;
            af[0] = Qs[r0];     af[1] = Qs[r0 + 288];
            af[2] = Qs[r0 + 4]; af[3] = Qs[r0 + 292];
            #pragma unroll
            for (int j = 0; j < 8; j++) {
                int b0 = (nb + j * 8 + g) * 36 + kc * 8 + ct;
                bf[j][0] = Kf[b0]; bf[j][1] = Kf[b0 + 4];
            }
            #pragma unroll
            for (int j = 0; j < 8; j++) mma16(c[j], af, bf[j]);
        }
        {
            int row = q0 + mb + g;
            #pragma unroll
            for (int j = 0; j < 8; j++) {
                int colg = n0 + nb + j * 8 + ct * 2;
                float2 mk0 = *(const float2*)&mask[(size_t)row * SS + colg];
                rs0 += fexp(fmaf(c[j][0], 0.125f, mk0.x))
                     + fexp(fmaf(c[j][1], 0.125f, mk0.y));
                float2 mk1 = *(const float2*)&mask[(size_t)(row + 8) * SS + colg];
                rs1 += fexp(fmaf(c[j][2], 0.125f, mk1.x))
                     + fexp(fmaf(c[j][3], 0.125f, mk1.y));
            }
        }
    }
    {
        float v = rs0;
        v += __shfl_xor_sync(0xffffffff, v, 1);
        v += __shfl_xor_sync(0xffffffff, v, 2);
        if (ct == 0) rowp[(mb + g) * 2 + nw] = v;
        v = rs1;
        v += __shfl_xor_sync(0xffffffff, v, 1);
        v += __shfl_xor_sync(0xffffffff, v, 2);
        if (ct == 0) rowp[(mb + 8 + g) * 2 + nw] = v;
    }
    __syncthreads();
    if (tid < 64) invs[tid] = 1.0f / (rowp[tid * 2] + rowp[tid * 2 + 1]);

    // ---------------- Pass B: score + ctx ----------------
    float d[8][4];
    #pragma unroll
    for (int j = 0; j < 8; j++)
        #pragma unroll
        for (int t = 0; t < 4; t++) d[j][t] = 0.0f;

    size_t sbase = (size_t)bh * SS * SS;

    KLOAD(0, 0);
    CP_COMMIT;
    for (int n0 = 0, st = 0; n0 < SS; n0 += 128, st ^= 1) {
        CP_WAIT0;            // K_cur ready (+ everything older)
        __syncthreads();     // prev PV readers of Vt done; invs visible (iter 0)
        VLOAD(n0);
        CP_COMMIT;
        if (n0 + 128 < SS) KLOAD(st ^ 1, n0 + 128);
        CP_COMMIT;

        const uint32_t* Kf = sm + AK + st * 4608;
        #pragma unroll
        for (int j = 0; j < 8; j++)
            #pragma unroll
            for (int t = 0; t < 4; t++) c[j][t] = 0.0f;
        #pragma unroll
        for (int kc = 0; kc < 4; kc++) {
            uint32_t af[4], bf[8][2];
            int r0 = (mb + g) * 36 + kc * 8 + ct;
            af[0] = Qs[r0];     af[1] = Qs[r0 + 288];
            af[2] = Qs[r0 + 4]; af[3] = Qs[r0 + 292];
            #pragma unroll
            for (int j = 0; j < 8; j++) {
                int b0 = (nb + j * 8 + g) * 36 + kc * 8 + ct;
                bf[j][0] = Kf[b0]; bf[j][1] = Kf[b0 + 4];
            }
            #pragma unroll
            for (int j = 0; j < 8; j++) mma16(c[j], af, bf[j]);
        }
        // epilogue: p -> score (fp32) + pack fp16 A-fragments in registers
        uint32_t plo[8], phi[8];
        {
            int rloc = mb + g;
            float iv0 = invs[rloc], iv1 = invs[rloc + 8];
            int grow = q0 + rloc;
            #pragma unroll
            for (int j = 0; j < 8; j++) {
                int colg = n0 + nb + j * 8 + ct * 2;
                float2 mk0 = *(const float2*)&mask[(size_t)grow * SS + colg];
                float p0 = fexp(fmaf(c[j][0], 0.125f, mk0.x)) * iv0;
                float p1 = fexp(fmaf(c[j][1], 0.125f, mk0.y)) * iv0;
                *(float2*)&score[sbase + (size_t)grow * SS + colg] = make_float2(p0, p1);
                float2 mk1 = *(const float2*)&mask[(size_t)(grow + 8) * SS + colg];
                float p2 = fexp(fmaf(c[j][2], 0.125f, mk1.x)) * iv1;
                float p3 = fexp(fmaf(c[j][3], 0.125f, mk1.y)) * iv1;
                *(float2*)&score[sbase + (size_t)(grow + 8) * SS + colg] = make_float2(p2, p3);
                plo[j] = h2u(__floats2half2_rn(p0, p1));
                phi[j] = h2u(__floats2half2_rn(p2, p3));
            }
        }
        CP_WAIT1;            // Vt done (K_next may remain in flight)
        __syncthreads();     // Vt visible to all
        // PV: ctx += P @ V ; A = packed p regs, B = V^T smem
        #pragma unroll
        for (int jj = 0; jj < 4; jj++) {
            uint32_t bf[8][2];
            #pragma unroll
            for (int jd = 0; jd < 8; jd++) {
                int b0 = (jd * 8 + g) * 68 + nw * 32 + jj * 8 + ct;
                bf[jd][0] = Vt[b0]; bf[jd][1] = Vt[b0 + 4];
            }
            uint32_t pa[4] = { plo[2 * jj], phi[2 * jj],
                               plo[2 * jj + 1], phi[2 * jj + 1] };
            #pragma unroll
            for (int jd = 0; jd < 8; jd++) mma16(d[jd], pa, bf[jd]);
        }
    }
    #undef KLOAD
    #undef VLOAD
    __syncthreads();
    // ctx reduction across the 2 n-strip warps (redc overlays dead Ks region)
    if (nw == 1) {
        int r0 = mb + g;
        #pragma unroll
        for (int jd = 0; jd < 8; jd++) {
            int col = jd * 8 + ct * 2;
            redc[r0 * 68 + col]           = d[jd][0];
            redc[r0 * 68 + col + 1]       = d[jd][1];
            redc[(r0 + 8) * 68 + col]     = d[jd][2];
            redc[(r0 + 8) * 68 + col + 1] = d[jd][3];
        }
    }
    __syncthreads();
    if (nw == 0) {
        int r0 = mb + g;
        #pragma unroll
        for (int jd = 0; jd < 8; jd++) {
            int col = jd * 8 + ct * 2;
            float v0 = d[jd][0] + redc[r0 * 68 + col];
            float v1 = d[jd][1] + redc[r0 * 68 + col + 1];
            float v2 = d[jd][2] + redc[(r0 + 8) * 68 + col];
            float v3 = d[jd][3] + redc[(r0 + 8) * 68 + col + 1];
            size_t b0 = ((size_t)bh * SS + q0 + r0) * DH + col;
            *(uint32_t*)&g_ctx[b0]          = h2u(__floats2half2_rn(v0, v1));
            *(uint32_t*)&g_ctx[b0 + 8 * DH] = h2u(__floats2half2_rn(v2, v3));
        }
    }
}

// ---------------------------------------------------------------------------
// K4: output projection, fp16. (unchanged from round 9)
// ---------------------------------------------------------------------------
__global__ __launch_bounds__(256, 2) void k_oproj(
    const float* __restrict__ bo, float* __restrict__ out)
{
    __shared__ uint32_t As[2][2560];
    __shared__ uint32_t Bs[2][2560];
    int tid = threadIdx.x;
    int lane = tid & 31, wid = tid >> 5;
    int g = lane >> 2, ct = lane & 3;
    int mb = (wid >> 2) * 64, nb = (wid & 3) * 32;
    int m0 = blockIdx.y * 128, n0 = blockIdx.x * 128;

    uint32_t asb = (uint32_t)__cvta_generic_to_shared(&As[0][0]);
    uint32_t bsb = (uint32_t)__cvta_generic_to_shared(&Bs[0][0]);

    float c[4][4][4];
    #pragma unroll
    for (int i = 0; i < 4; i++)
        #pragma unroll
        for (int j = 0; j < 4; j++)
            #pragma unroll
            for (int t = 0; t < 4; t++) c[i][j][t] = 0.0f;

    #define OLOAD(st_, k0_) do {                                                \
        _Pragma("unroll")                                                       \
        for (int it = 0; it < 2; it++) {                                        \
            int sl = tid + it * 256;                                            \
            int r = sl >> 2, ch = sl & 3;                                       \
            int m = m0 + r;                                                     \
            int b_ = m >> 11, s_ = m & (SS - 1);                                \
            int kk = (k0_) + ch * 8;                                            \
            int h = kk >> 6, dhh = kk & 63;                                     \
            cpa16(asb + ((st_) * 2560 + r * 20 + ch * 4) * 4,                   \
                  g_ctx + ((size_t)(b_ * HH + h) * SS + s_) * DH + dhh);        \
            cpa16(bsb + ((st_) * 2560 + r * 20 + ch * 4) * 4,                   \
                  g_wh3 + (size_t)(n0 + r) * DM + (k0_) + ch * 8);              \
        }                                                                       \
    } while (0)

    OLOAD(0, 0);
    CP_COMMIT;

    for (int k0 = 0, st = 0; k0 < DM; k0 += 32, st ^= 1) {
        CP_WAIT0;
        __syncthreads();
        if (k0 + 32 < DM) OLOAD(st ^ 1, k0 + 32);
        CP_COMMIT;
        const uint32_t* Af = &As[st][0];
        const uint32_t* Bf = &Bs[st][0];
        #pragma unroll
        for (int kc = 0; kc < 2; kc++) {
            uint32_t af[4][4], bf[4][2];
            #pragma unroll
            for (int i = 0; i < 4; i++) {
                int r0 = (mb + i * 16 + g) * 20 + kc * 8 + ct;
                af[i][0] = Af[r0];     af[i][1] = Af[r0 + 160];
                af[i][2] = Af[r0 + 4]; af[i][3] = Af[r0 + 164];
            }
            #pragma unroll
            for (int j = 0; j < 4; j++) {
                int b0 = (nb + j * 8 + g) * 20 + kc * 8 + ct;
                bf[j][0] = Bf[b0]; bf[j][1] = Bf[b0 + 4];
            }
            #pragma unroll
            for (int i = 0; i < 4; i++)
                #pragma unroll
                for (int j = 0; j < 4; j++) mma16(c[i][j], af[i], bf[j]);
        }
    }
    #undef OLOAD
    __syncthreads();
    #pragma unroll
    for (int i = 0; i < 4; i++) {
        int row = m0 + mb + i * 16 + g;
        #pragma unroll
        for (int j = 0; j < 4; j++) {
            int col = n0 + nb + j * 8 + ct * 2;
            float2 bi = *(const float2*)&bo[col];
            *(float2*)&out[(size_t)row * DM + col] =
                make_float2(c[i][j][0] + bi.x, c[i][j][1] + bi.y);
            *(float2*)&out[(size_t)(row + 8) * DM + col] =
                make_float2(c[i][j][2] + bi.x, c[i][j][3] + bi.y);
        }
    }
}

// ---------------------------------------------------------------------------
extern "C" void kernel_launch(void* const* d_in, const int* in_sizes, int n_in,
                              void* d_out, int out_size)
{
    const float* q    = (const float*)d_in[0];
    const float* k    = (const float*)d_in[1];
    const float* v    = (const float*)d_in[2];
    const float* mask = (const float*)d_in[3];
    const float* w_q  = (const float*)d_in[4];
    const float* b_q  = (const float*)d_in[5];
    const float* w_k  = (const float*)d_in[6];
    const float* b_k  = (const float*)d_in[7];
    const float* w_v  = (const float*)d_in[8];
    const float* b_v  = (const float*)d_in[9];
    const float* w_o  = (const float*)d_in[10];
    const float* b_o  = (const float*)d_in[11];

    float* out   = (float*)d_out;                        // x: [B,S,DM]
    float* score = out + (size_t)BB * SS * DM;           // score: [B,H,S,S]

    cudaFuncSetAttribute(k_attn, cudaFuncAttributeMaxDynamicSharedMemorySize, AT_BYTES);

    k_prep<<<dim3(4096, 1, 7), 512>>>(q, k, v, w_q, w_k, w_v, w_o);
    k_qkv_proj<<<dim3(DM/128, (BB*SS)/128, 3), 256>>>(b_q, b_k, b_v);
    k_attn<<<dim3(SS/64, BHT), 256, AT_BYTES>>>(mask, score);
    k_oproj<<<dim3(DM/128, (BB*SS)/128), 256>>>(b_o, out);
}